// round 16
// baseline (speedup 1.0000x reference)
#include <cuda_runtime.h>
#include <cuda_bf16.h>
#include <cstdint>
#include <cstddef>

#define N_USERS   100000
#define N_NODES   500000
#define DIM       64
#define N_EDGES   2000000
#define BATCH     4096
#define NWORDS    ((N_NODES + 31) / 32)
#define GRID      592          // 4 blocks/SM x 148 SMs -> always fully resident
#define TPB       256
#define NCH       (N_EDGES / 8)   // 250000 8-edge chunks

// -------- device scratch (static, allocation-free) --------
// ZERO-RESTORE INVARIANT: __device__ globals are zero-initialized at module
// load; every array mutated during a call is restored to zero by the end of
// the same call (deg in the dinv phase, fb/ncnt/ecnt in the loss phase, the
// barrier counter self-restores). g_gen grows monotonically across calls —
// the equality-spin barrier is generation-relative so that's fine.
__device__ __nv_bfloat16 g_XA[(size_t)N_NODES * DIM];
__device__ __nv_bfloat16 g_XB[(size_t)N_NODES * DIM];
__device__ __nv_bfloat16 g_XC[(size_t)N_NODES * DIM];
__device__ float    g_dinv[N_NODES];
__device__ unsigned g_deg[N_NODES];
__device__ unsigned g_fb[3][NWORDS];
__device__ int      g_nl[3][N_NODES];
__device__ int      g_ncnt[3];
__device__ int2     g_le[3][N_EDGES];
__device__ int      g_ecnt[3];
__device__ unsigned g_cnt;                 // barrier arrivals (self-restoring)
__device__ volatile unsigned g_gen;        // barrier generation (monotonic)

__device__ __forceinline__ __nv_bfloat16* xbuf(int sel) {
    return sel == 1 ? g_XA : (sel == 2 ? g_XB : g_XC);
}

// software grid barrier: safe because GRID (592) <= guaranteed-resident blocks
// (launch_bounds(256,4) -> 4 blocks/SM x 148 SMs).
__device__ __forceinline__ void gsync() {
    __threadfence();
    __syncthreads();
    if (threadIdx.x == 0) {
        unsigned gen = g_gen;
        if (atomicAdd(&g_cnt, 1u) == gridDim.x - 1u) {
            g_cnt = 0u;
            __threadfence();
            g_gen = gen + 1u;
        } else {
            while (g_gen == gen) { }
        }
    }
    __syncthreads();
    __threadfence();
}

// warp-aggregated single-item append
__device__ __forceinline__ int wagg_append(int* counter, bool pred) {
    unsigned mask = __ballot_sync(0xffffffffu, pred);
    if (!pred) return -1;
    int lane   = threadIdx.x & 31;
    int leader = __ffs(mask) - 1;
    int rank   = __popc(mask & ((1u << lane) - 1));
    int base = 0;
    if (lane == leader) base = atomicAdd(counter, __popc(mask));
    base = __shfl_sync(mask, base, leader);
    return base + rank;
}

// warp-scan multi-append: ONE atomic per warp; all lanes participate
__device__ __forceinline__ int wscan_append(int* counter, int cnt) {
    int lane = threadIdx.x & 31;
    int incl = cnt;
#pragma unroll
    for (int o = 1; o < 32; o <<= 1) {
        int v = __shfl_up_sync(0xffffffffu, incl, o);
        if (lane >= o) incl += v;
    }
    int total = __shfl_sync(0xffffffffu, incl, 31);
    int base = 0;
    if (lane == 31 && total) base = atomicAdd(counter, total);
    base = __shfl_sync(0xffffffffu, base, 31);
    return base + incl - cnt;
}

__device__ __forceinline__ bool mark_node(int L, int idx) {
    unsigned bit = 1u << (idx & 31);
    unsigned old = atomicOr(&g_fb[L][idx >> 5], bit);
    return (old & bit) == 0u;
}

__device__ __forceinline__ bool test_node(int L, int idx) {
    return (g_fb[L][idx >> 5] >> (idx & 31)) & 1u;
}

// compaction phase: 8 edges/chunk-thread, uniform trip count (warp-safe).
__device__ void phase_compact(const int* __restrict__ src,
                              const int* __restrict__ dst,
                              int gate, int prev, bool has_prev, bool do_deg,
                              int gtid, int gsz) {
    int iters = (NCH + gsz - 1) / gsz;
    for (int it = 0; it < iters; it++) {
        int t = gtid + it * gsz;
        bool inb = (t < NCH);
        int4 dA = make_int4(0,0,0,0), dB = make_int4(0,0,0,0);
        if (inb) {
            dA = __ldg((const int4*)dst + 2 * t);
            dB = __ldg((const int4*)dst + 2 * t + 1);
        }
        int dd[8] = {dA.x, dA.y, dA.z, dA.w, dB.x, dB.y, dB.z, dB.w};

        if (do_deg && inb) {
#pragma unroll
            for (int i = 0; i < 8; i++)
                atomicAdd(&g_deg[dd[i]], 1u);
        }

        bool p[8];
        int cnt = 0;
#pragma unroll
        for (int i = 0; i < 8; i++) {
            p[i] = inb && test_node(gate, dd[i]);
            cnt += p[i];
        }
        int4 sA = make_int4(0,0,0,0), sB = make_int4(0,0,0,0);
        if (cnt) {
            sA = __ldg((const int4*)src + 2 * t);
            sB = __ldg((const int4*)src + 2 * t + 1);
        }
        int ss[8] = {sA.x, sA.y, sA.z, sA.w, sB.x, sB.y, sB.z, sB.w};

        int off = wscan_append(&g_ecnt[gate], cnt);
#pragma unroll
        for (int i = 0; i < 8; i++)
            if (p[i]) g_le[gate][off++] = make_int2(ss[i], dd[i]);

        if (has_prev) {
            bool nw[8];
            int ncnt = 0;
#pragma unroll
            for (int i = 0; i < 8; i++) {
                nw[i] = p[i] && mark_node(prev, ss[i]);
                ncnt += nw[i];
            }
            int noff = wscan_append(&g_ncnt[prev], ncnt);
#pragma unroll
            for (int i = 0; i < 8; i++)
                if (nw[i]) g_nl[prev][noff++] = ss[i];
        }
    }
}

// propagation phase over compact edge list: 8 lanes/edge, grid-stride.
// xsel==0: gather fp32 emb (32B/lane), convert inline; else bf16 buffers.
__device__ void phase_prop(const float* __restrict__ emb,
                           int xsel, int ysel, int lsel, int gtid, int gsz) {
    int m = g_ecnt[lsel] * 8;
    uint4* y = (uint4*)xbuf(ysel);
    for (int t = gtid; t < m; t += gsz) {
        int e = t >> 3, lane = t & 7;
        int2  sd = __ldg(&g_le[lsel][e]);
        float w = __ldg(g_dinv + sd.x) * __ldg(g_dinv + sd.y);
        __nv_bfloat162 q0, q1, q2, q3;
        if (xsel == 0) {
            const float4* xf = (const float4*)emb + (size_t)sd.x * 16 + lane * 2;
            float4 a = __ldg(xf);
            float4 b = __ldg(xf + 1);
            q0 = __float22bfloat162_rn(make_float2(a.x * w, a.y * w));
            q1 = __float22bfloat162_rn(make_float2(a.z * w, a.w * w));
            q2 = __float22bfloat162_rn(make_float2(b.x * w, b.y * w));
            q3 = __float22bfloat162_rn(make_float2(b.z * w, b.w * w));
        } else {
            const uint4* x = (const uint4*)xbuf(xsel);
            uint4 v = __ldg(x + (size_t)sd.x * 8 + lane);
            __nv_bfloat162 w2 = __float2bfloat162_rn(w);
            q0 = __hmul2(*(__nv_bfloat162*)&v.x, w2);
            q1 = __hmul2(*(__nv_bfloat162*)&v.y, w2);
            q2 = __hmul2(*(__nv_bfloat162*)&v.z, w2);
            q3 = __hmul2(*(__nv_bfloat162*)&v.w, w2);
        }
        uint4* a = y + (size_t)sd.y * 8 + lane;
        asm volatile("red.global.add.noftz.v4.bf16x2 [%0], {%1, %2, %3, %4};"
                     :: "l"(a), "r"(*(unsigned*)&q0), "r"(*(unsigned*)&q1),
                        "r"(*(unsigned*)&q2), "r"(*(unsigned*)&q3)
                     : "memory");
    }
}

// -------- THE mega-kernel: all phases, software grid barriers between --------
__global__ void __launch_bounds__(TPB, 4)
k_mega(const float* __restrict__ emb,
       const int* __restrict__ src, const int* __restrict__ dst,
       const int* __restrict__ user, const int* __restrict__ pos,
       const int* __restrict__ neg, float* __restrict__ out) {
    int gtid = blockIdx.x * blockDim.x + threadIdx.x;
    int gsz  = gridDim.x * blockDim.x;   // 151552

    // ---- phase 1: mark batch nodes (all 3 levels) + zero out ----
    if (gtid == 0) out[0] = 0.0f;
    {
        int t = gtid;                    // 9*BATCH = 36864 < gsz: single pass
        bool act = (t < 9 * BATCH);
        int L = 0, idx = 0;
        if (act) {
            L = t / (3 * BATCH);
            int r = t - L * (3 * BATCH);
            idx = (r < BATCH) ? user[r]
                : (r < 2 * BATCH) ? pos[r - BATCH]
                                  : neg[r - 2 * BATCH];
            act = mark_node(L, idx);
        }
#pragma unroll
        for (int LL = 0; LL < 3; LL++) {
            bool pred = act && (L == LL);
            int slot = wagg_append(&g_ncnt[LL], pred);
            if (pred) g_nl[LL][slot] = idx;
        }
    }
    gsync();

    // ---- phase 2: compactA (gate fb2 -> list2; mark fb1+nl1; accumulate deg)
    phase_compact(src, dst, 2, 1, true, true, gtid, gsz);
    gsync();

    // ---- phase 3: dinv (+deg restore) and compactB (gate fb1 -> list1; mark fb0+nl0)
    for (int i = gtid; i < N_NODES; i += gsz) {
        unsigned d = g_deg[i];
        g_dinv[i] = d ? rsqrtf((float)d) : 0.0f;
        g_deg[i] = 0u;
    }
    phase_compact(src, dst, 1, 0, true, false, gtid, gsz);
    gsync();

    // ---- phase 4: zero flagged rows of XA/XB/XC and compactC (gate fb0 -> list0)
    {
        int n0 = g_ncnt[0] * 8, n1 = g_ncnt[1] * 8, n2 = g_ncnt[2] * 8;
        int ntot = n0 + n1 + n2;
        for (int t = gtid; t < ntot; t += gsz) {
            uint4* y; int r, c;
            if (t < n0)           { y = (uint4*)g_XA; r = g_nl[0][t >> 3]; c = t & 7; }
            else if (t < n0 + n1) { int q = t - n0;
                                    y = (uint4*)g_XB; r = g_nl[1][q >> 3]; c = q & 7; }
            else                  { int q = t - n0 - n1;
                                    y = (uint4*)g_XC; r = g_nl[2][q >> 3]; c = q & 7; }
            y[(size_t)r * 8 + c] = make_uint4(0u, 0u, 0u, 0u);
        }
    }
    phase_compact(src, dst, 0, 0, false, false, gtid, gsz);
    gsync();

    // ---- phases 5-7: the three propagation layers ----
    phase_prop(emb, 0, 1, 0, gtid, gsz);   // emb -> XA over list0
    gsync();
    phase_prop(emb, 1, 2, 1, gtid, gsz);   // XA  -> XB over list1
    gsync();
    phase_prop(emb, 2, 3, 2, gtid, gsz);   // XB  -> XC over list2
    gsync();

    // ---- phase 8: loss + zero-state restore ----
    if (gtid < NWORDS) { g_fb[0][gtid] = 0u; g_fb[1][gtid] = 0u; g_fb[2][gtid] = 0u; }
    if (gtid < 3) { g_ncnt[gtid] = 0; g_ecnt[gtid] = 0; }

    int w = gtid >> 5;
    int lane = threadIdx.x & 31;
    if (w < BATCH) {
        int ui = user[w], pi = pos[w], ni = neg[w];
        const float2* E = (const float2*)emb;
        const __nv_bfloat162* A = (const __nv_bfloat162*)g_XA;
        const __nv_bfloat162* B = (const __nv_bfloat162*)g_XB;
        const __nv_bfloat162* C = (const __nv_bfloat162*)g_XC;
        size_t uo = (size_t)ui * 32 + lane;
        size_t po = (size_t)pi * 32 + lane;
        size_t no = (size_t)ni * 32 + lane;

        float2 eu = __ldg(E + uo), ep = __ldg(E + po), en = __ldg(E + no);
        float2 au = __bfloat1622float2(A[uo]), bu = __bfloat1622float2(B[uo]),
               cu = __bfloat1622float2(C[uo]);
        float2 ap = __bfloat1622float2(A[po]), bp = __bfloat1622float2(B[po]),
               cp = __bfloat1622float2(C[po]);
        float2 an = __bfloat1622float2(A[no]), bn = __bfloat1622float2(B[no]),
               cn = __bfloat1622float2(C[no]);

        float ux = eu.x + au.x + bu.x + cu.x, uy = eu.y + au.y + bu.y + cu.y;
        float px = ep.x + ap.x + bp.x + cp.x, py = ep.y + ap.y + bp.y + cp.y;
        float nx = en.x + an.x + bn.x + cn.x, ny = en.y + an.y + bn.y + cn.y;

        float pd = ux * px + uy * py;
        float nd = ux * nx + uy * ny;
        float sq = eu.x * eu.x + eu.y * eu.y
                 + ep.x * ep.x + ep.y * ep.y
                 + en.x * en.x + en.y * en.y;
#pragma unroll
        for (int o = 16; o; o >>= 1) {
            pd += __shfl_xor_sync(0xffffffffu, pd, o);
            nd += __shfl_xor_sync(0xffffffffu, nd, o);
            sq += __shfl_xor_sync(0xffffffffu, sq, o);
        }
        if (lane == 0) {
            float z = (nd - pd) * 0.0625f;                       // /16 for mean^2
            float sp = fmaxf(z, 0.f) + log1pf(expf(-fabsf(z)));  // softplus(neg-pos)
            atomicAdd(out, (sp + 5e-5f * sq) * (1.0f / BATCH));  // + L2_REG*0.5/BATCH
        }
    }
}

extern "C" void kernel_launch(void* const* d_in, const int* in_sizes, int n_in,
                              void* d_out, int out_size) {
    const float* emb  = (const float*)d_in[0];
    const int*   edge = (const int*)d_in[1];
    const int*   src  = edge;
    const int*   dst  = edge + N_EDGES;
    const int*   user = (const int*)d_in[2];
    const int*   pos  = (const int*)d_in[3];
    const int*   neg  = (const int*)d_in[4];
    float*       out  = (float*)d_out;

    k_mega<<<GRID, TPB>>>(emb, src, dst, user, pos, neg, out);
}

// round 17
// speedup vs baseline: 1.2196x; 1.2196x over previous
#include <cuda_runtime.h>
#include <cuda_bf16.h>
#include <cstdint>
#include <cstddef>

#define N_USERS   100000
#define N_NODES   500000
#define DIM       64
#define N_EDGES   2000000
#define BATCH     4096
#define NWORDS    ((N_NODES + 31) / 32)

// -------- device scratch (static, allocation-free) --------
// NOTE: never touch these symbols from host code (GB300 ATS would silently
// route through the host shadow at 200GB/s). All access via device selectors.
// ZERO-RESTORE INVARIANT: __device__ globals are zero-initialized at module
// load; every array mutated during a call is restored to zero by the end of
// the same call (deg in k_dinv, fb/ecnt in k_loss). No init kernel needed.
__device__ __nv_bfloat16 g_XA[(size_t)N_NODES * DIM];  // bf16 layer buffers
__device__ __nv_bfloat16 g_XB[(size_t)N_NODES * DIM];
__device__ __nv_bfloat16 g_XC[(size_t)N_NODES * DIM];
__device__ float    g_dinv[N_NODES];
__device__ unsigned g_deg[N_NODES];
__device__ unsigned g_fb[3][NWORDS];       // needed-node bitmasks (L2-resident)
__device__ int2     g_le[3][N_EDGES];      // compact edge lists (src,dst)
__device__ int      g_ecnt[3];

__device__ __forceinline__ __nv_bfloat16* xbuf(int sel) {
    return sel == 1 ? g_XA : (sel == 2 ? g_XB : g_XC);
}

// dinv = rsqrt(deg); also RESTORES deg to 0 for the next invocation
__global__ void k_dinv() {
    int i = blockIdx.x * blockDim.x + threadIdx.x;
    if (i < N_NODES) {
        unsigned d = g_deg[i];
        g_dinv[i] = d ? rsqrtf((float)d) : 0.0f;
        g_deg[i] = 0u;
    }
}

// warp-scan multi-append: ONE atomic per warp; all lanes participate
__device__ __forceinline__ int wscan_append(int* counter, int cnt) {
    int lane = threadIdx.x & 31;
    int incl = cnt;
#pragma unroll
    for (int o = 1; o < 32; o <<= 1) {
        int v = __shfl_up_sync(0xffffffffu, incl, o);
        if (lane >= o) incl += v;
    }
    int total = __shfl_sync(0xffffffffu, incl, 31);
    int base = 0;
    if (lane == 31 && total) base = atomicAdd(counter, total);
    base = __shfl_sync(0xffffffffu, base, 31);
    return base + incl - cnt;
}

__device__ __forceinline__ void set_node(int L, int idx) {
    atomicOr(&g_fb[L][idx >> 5], 1u << (idx & 31));
}

__device__ __forceinline__ bool test_node(int L, int idx) {
    return (g_fb[L][idx >> 5] >> (idx & 31)) & 1u;
}

// mark batch nodes in all 3 bitmasks (no lists); also zero the output scalar
__global__ void k_mark_batch(const int* __restrict__ u,
                             const int* __restrict__ p,
                             const int* __restrict__ n,
                             float* __restrict__ out) {
    int t = blockIdx.x * blockDim.x + threadIdx.x;
    if (t == 0) out[0] = 0.0f;
    if (t >= 3 * BATCH) return;
    int idx = (t < BATCH) ? u[t]
            : (t < 2 * BATCH) ? p[t - BATCH]
                              : n[t - 2 * BATCH];
    set_node(0, idx); set_node(1, idx); set_node(2, idx);
}

// compaction, 8 edges/thread, ONE warp-scan append per iteration.
// pass: f[gate][dst] && (excl < 0 || !f[excl][dst]).
// optionally mark sources one layer earlier; optionally accumulate degree.
__global__ void k_compact8s(const int* __restrict__ src, const int* __restrict__ dst,
                            int gate, int excl, int prev, int has_prev, int do_deg) {
    int t = blockIdx.x * blockDim.x + threadIdx.x;
    bool inb = (t < N_EDGES / 8);
    int4 dA = make_int4(0,0,0,0), dB = make_int4(0,0,0,0);
    if (inb) {
        dA = __ldg((const int4*)dst + 2 * t);
        dB = __ldg((const int4*)dst + 2 * t + 1);
    }
    int dd[8] = {dA.x, dA.y, dA.z, dA.w, dB.x, dB.y, dB.z, dB.w};

    if (do_deg && inb) {
#pragma unroll
        for (int i = 0; i < 8; i++)
            atomicAdd(&g_deg[dd[i]], 1u);
    }

    bool p[8];
    int cnt = 0;
#pragma unroll
    for (int i = 0; i < 8; i++) {
        p[i] = inb && test_node(gate, dd[i]);
        if (excl >= 0 && p[i]) p[i] = !test_node(excl, dd[i]);
        cnt += p[i];
    }
    int4 sA = make_int4(0,0,0,0), sB = make_int4(0,0,0,0);
    if (cnt) {
        sA = __ldg((const int4*)src + 2 * t);
        sB = __ldg((const int4*)src + 2 * t + 1);
    }
    int ss[8] = {sA.x, sA.y, sA.z, sA.w, sB.x, sB.y, sB.z, sB.w};

    int off = wscan_append(&g_ecnt[gate], cnt);
#pragma unroll
    for (int i = 0; i < 8; i++)
        if (p[i]) g_le[gate][off++] = make_int2(ss[i], dd[i]);

    if (has_prev) {
#pragma unroll
        for (int i = 0; i < 8; i++)          // independent atomicOr ops, MLP=8
            if (p[i]) set_node(prev, ss[i]);
    }
}

// zero flagged rows of XA/XB/XC by scanning the bitmasks directly.
// one thread per node; warp-adjacent nodes share the fb word (L1 broadcast).
__global__ void k_zero_all() {
    int stride = gridDim.x * blockDim.x;
    const uint4 z = make_uint4(0u, 0u, 0u, 0u);
    for (int i = blockIdx.x * blockDim.x + threadIdx.x; i < N_NODES; i += stride) {
        unsigned w0 = g_fb[0][i >> 5], w1 = g_fb[1][i >> 5], w2 = g_fb[2][i >> 5];
        unsigned bit = 1u << (i & 31);
        if (w0 & bit) {
            uint4* y = (uint4*)g_XA + (size_t)i * 8;
#pragma unroll
            for (int c = 0; c < 8; c++) y[c] = z;
        }
        if (w1 & bit) {
            uint4* y = (uint4*)g_XB + (size_t)i * 8;
#pragma unroll
            for (int c = 0; c < 8; c++) y[c] = z;
        }
        if (w2 & bit) {
            uint4* y = (uint4*)g_XC + (size_t)i * 8;
#pragma unroll
            for (int c = 0; c < 8; c++) y[c] = z;
        }
    }
}

// propagation over compact edge list: 8 lanes/edge, grid-stride.
// xsel==0: gather fp32 emb directly (32B/lane), convert inline; else bf16.
__global__ void k_prop_list(const float* __restrict__ emb,
                            int xsel, int ysel, int lsel) {
    int m = g_ecnt[lsel] * 8;
    uint4* y = (uint4*)xbuf(ysel);
    int stride = gridDim.x * blockDim.x;
    for (int t = blockIdx.x * blockDim.x + threadIdx.x; t < m; t += stride) {
        int e = t >> 3, lane = t & 7;
        int2  sd = __ldg(&g_le[lsel][e]);
        float w = __ldg(g_dinv + sd.x) * __ldg(g_dinv + sd.y);
        __nv_bfloat162 q0, q1, q2, q3;
        if (xsel == 0) {
            const float4* xf = (const float4*)emb + (size_t)sd.x * 16 + lane * 2;
            float4 a = __ldg(xf);
            float4 b = __ldg(xf + 1);
            q0 = __float22bfloat162_rn(make_float2(a.x * w, a.y * w));
            q1 = __float22bfloat162_rn(make_float2(a.z * w, a.w * w));
            q2 = __float22bfloat162_rn(make_float2(b.x * w, b.y * w));
            q3 = __float22bfloat162_rn(make_float2(b.z * w, b.w * w));
        } else {
            const uint4* x = (const uint4*)xbuf(xsel);
            uint4 v = __ldg(x + (size_t)sd.x * 8 + lane);
            __nv_bfloat162 w2 = __float2bfloat162_rn(w);
            q0 = __hmul2(*(__nv_bfloat162*)&v.x, w2);
            q1 = __hmul2(*(__nv_bfloat162*)&v.y, w2);
            q2 = __hmul2(*(__nv_bfloat162*)&v.z, w2);
            q3 = __hmul2(*(__nv_bfloat162*)&v.w, w2);
        }
        uint4* a = y + (size_t)sd.y * 8 + lane;
        asm volatile("red.global.add.noftz.v4.bf16x2 [%0], {%1, %2, %3, %4};"
                     :: "l"(a), "r"(*(unsigned*)&q0), "r"(*(unsigned*)&q1),
                        "r"(*(unsigned*)&q2), "r"(*(unsigned*)&q3)
                     : "memory");
    }
}

// -------- fused final loss + state restore --------
__global__ void k_loss(const float* __restrict__ emb,
                       const int* __restrict__ user,
                       const int* __restrict__ pos,
                       const int* __restrict__ neg,
                       float* __restrict__ out) {
    int gt = blockIdx.x * blockDim.x + threadIdx.x;

    // restore zero-state for the next invocation (fb + edge counters)
    if (gt < NWORDS) { g_fb[0][gt] = 0u; g_fb[1][gt] = 0u; g_fb[2][gt] = 0u; }
    if (gt < 3) g_ecnt[gt] = 0;

    int w = gt >> 5;
    int lane = threadIdx.x & 31;
    if (w >= BATCH) return;

    int ui = user[w], pi = pos[w], ni = neg[w];

    const float2* E = (const float2*)emb;
    const __nv_bfloat162* A = (const __nv_bfloat162*)g_XA;
    const __nv_bfloat162* B = (const __nv_bfloat162*)g_XB;
    const __nv_bfloat162* C = (const __nv_bfloat162*)g_XC;

    size_t uo = (size_t)ui * 32 + lane;
    size_t po = (size_t)pi * 32 + lane;
    size_t no = (size_t)ni * 32 + lane;

    float2 eu = __ldg(E + uo), ep = __ldg(E + po), en = __ldg(E + no);
    float2 au = __bfloat1622float2(A[uo]), bu = __bfloat1622float2(B[uo]),
           cu = __bfloat1622float2(C[uo]);
    float2 ap = __bfloat1622float2(A[po]), bp = __bfloat1622float2(B[po]),
           cp = __bfloat1622float2(C[po]);
    float2 an = __bfloat1622float2(A[no]), bn = __bfloat1622float2(B[no]),
           cn = __bfloat1622float2(C[no]);

    float ux = eu.x + au.x + bu.x + cu.x, uy = eu.y + au.y + bu.y + cu.y;
    float px = ep.x + ap.x + bp.x + cp.x, py = ep.y + ap.y + bp.y + cp.y;
    float nx = en.x + an.x + bn.x + cn.x, ny = en.y + an.y + bn.y + cn.y;

    float pd = ux * px + uy * py;
    float nd = ux * nx + uy * ny;
    float sq = eu.x * eu.x + eu.y * eu.y
             + ep.x * ep.x + ep.y * ep.y
             + en.x * en.x + en.y * en.y;

#pragma unroll
    for (int o = 16; o; o >>= 1) {
        pd += __shfl_xor_sync(0xffffffffu, pd, o);
        nd += __shfl_xor_sync(0xffffffffu, nd, o);
        sq += __shfl_xor_sync(0xffffffffu, sq, o);
    }
    if (lane == 0) {
        float z = (nd - pd) * 0.0625f;                       // /16 for mean^2
        float sp = fmaxf(z, 0.f) + log1pf(expf(-fabsf(z)));  // softplus(neg-pos)
        atomicAdd(out, (sp + 5e-5f * sq) * (1.0f / BATCH));  // + L2_REG*0.5/BATCH
    }
}

extern "C" void kernel_launch(void* const* d_in, const int* in_sizes, int n_in,
                              void* d_out, int out_size) {
    const float* emb  = (const float*)d_in[0];
    const int*   edge = (const int*)d_in[1];
    const int*   src  = edge;
    const int*   dst  = edge + N_EDGES;
    const int*   user = (const int*)d_in[2];
    const int*   pos  = (const int*)d_in[3];
    const int*   neg  = (const int*)d_in[4];
    float*       out  = (float*)d_out;

    static cudaStream_t s1 = nullptr, s2 = nullptr;
    static cudaEvent_t evA, evB, evZ, evP1;
    if (!s1) {
        cudaStreamCreateWithFlags(&s1, cudaStreamNonBlocking);
        cudaStreamCreateWithFlags(&s2, cudaStreamNonBlocking);
        cudaEventCreateWithFlags(&evA,  cudaEventDisableTiming);
        cudaEventCreateWithFlags(&evB,  cudaEventDisableTiming);
        cudaEventCreateWithFlags(&evZ,  cudaEventDisableTiming);
        cudaEventCreateWithFlags(&evP1, cudaEventDisableTiming);
    }

    const int T = 256;
    const int G_NODES = (N_NODES + T - 1) / T;
    const int G_CMP   = (N_EDGES / 8 + T - 1) / T;
    const int G_MARK  = (3 * BATCH + T - 1) / T;
    const int G_PROP  = 2048;
    const int G_ZERO  = 1024;
    const int G_LOSS  = (BATCH * 32 + T - 1) / T;   // covers NWORDS too

    // origin stream: serial critical chain (mark -> compacts)
    k_mark_batch<<<G_MARK, T>>>(user, pos, neg, out);
    // compactA also accumulates degree
    k_compact8s<<<G_CMP, T>>>(src, dst, 2, -1, 1, 1, 1); // list2; mark fb1; deg
    cudaEventRecord(evA, 0);
    k_compact8s<<<G_CMP, T>>>(src, dst, 1, -1, 0, 1, 0); // list1; mark fb0
    cudaEventRecord(evB, 0);
    // compactC overlapped with zero_all (s2) and prop1a (s1): f0 && !f1 edges
    k_compact8s<<<G_CMP, T>>>(src, dst, 0, 1, 0, 0, 0);  // -> list0

    // s1: dinv after compactA's degree accumulation (also restores deg=0)
    cudaStreamWaitEvent(s1, evA, 0);
    k_dinv<<<G_NODES, T, 0, s1>>>();

    // s2: bitmask-driven zero once all fb marks are final (evB)
    cudaStreamWaitEvent(s2, evB, 0);
    k_zero_all<<<G_ZERO, T, 0, s2>>>();
    cudaEventRecord(evZ, s2);

    // prop1a on s1: fp32 emb -> XA over list1 edges, overlapped with compactC
    cudaStreamWaitEvent(s1, evZ, 0);
    k_prop_list<<<G_PROP, T, 0, s1>>>(emb, 0, 1, 1);
    cudaEventRecord(evP1, s1);

    // join onto origin
    cudaStreamWaitEvent(0, evZ, 0);
    cudaStreamWaitEvent(0, evP1, 0);

    // prop1b: remaining layer-1 edges (f0 && !f1) -> XA, fp32 gather
    k_prop_list<<<G_PROP, T>>>(emb, 0, 1, 0);
    // layers 2/3 (bf16 gather)
    k_prop_list<<<G_PROP, T>>>(emb, 1, 2, 1);       // XA -> XB over list1
    k_prop_list<<<G_PROP, T>>>(emb, 2, 3, 2);       // XB -> XC over list2

    // fused loss + zero-state restore
    k_loss<<<G_LOSS, T>>>(emb, user, pos, neg, out);
}